// round 15
// baseline (speedup 1.0000x reference)
#include <cuda_runtime.h>
#include <cstdint>

// PointwiseConvBlurModel: spatially-varying 17x17 blur.
// out[b,c,y,x] = sum_{kh,kw} kern[kh*17+kw, y*256+x] * img[b,c,y+kh,x+kw]
// kern = kernels[idx[0], 0]
//
// R12: double-buffered cp.async weight pipeline. Per kh, the tile's weight
// slab (17 taps x 4 rows x 128B = 8.7KB) is staged into SMEM two stages
// ahead; compute consumes weights via conflict-free LDS.128 instead of
// waiting ~600cyc on the compulsory-miss DRAM stream every kh.

#define KS      17
#define HP      256
#define WP      256
#define PIX     (HP * WP)       // 65536
#define IH      (HP + KS - 1)   // 272
#define IW      (WP + KS - 1)   // 272
#define TH      4               // output tile height
#define TW      32              // output tile width
#define SROWS   (TH + KS - 1)   // 20
#define SCOLS   (TW + KS - 1)   // 48
#define NBC     12              // B*C planes
#define GROUPS  3
#define PL      (NBC / GROUPS)  // 4 planes per thread
#define PXT     (TH * TW / 4)   // 32 px-threads per group (1 warp)
#define THREADS (PXT * GROUPS)  // 96

#define IMG_FLOATS  (NBC * SROWS * SCOLS)   // 11520
#define WSTAGE_FLT  (KS * TH * TW)          // 2176 floats = 8704 B per stage
#define WGRAN       (WSTAGE_FLT / 4)        // 544 x 16B granules per stage
#define SMEM_BYTES  ((IMG_FLOATS + 2 * WSTAGE_FLT) * 4)  // 63488

__device__ __forceinline__ void cp_async16(uint32_t dst_smem, const float* src) {
    asm volatile("cp.async.cg.shared.global [%0], [%1], 16;\n"
                 :: "r"(dst_smem), "l"(src));
}
__device__ __forceinline__ void cp_commit() {
    asm volatile("cp.async.commit_group;\n" ::: "memory");
}
template <int N>
__device__ __forceinline__ void cp_wait() {
    asm volatile("cp.async.wait_group %0;\n" :: "n"(N) : "memory");
}

__global__ __launch_bounds__(THREADS, 3)
void blur_tiled_kernel(const float* __restrict__ img,
                       const float* __restrict__ kernels,
                       const int*   __restrict__ idx,
                       float*       __restrict__ out)
{
    extern __shared__ float smem[];
    float* simg = smem;                      // [NBC][SROWS][SCOLS]
    float* wbuf = smem + IMG_FLOATS;         // [2][KS][TH][TW]

    const int tile = blockIdx.x;
    const int x0 = (tile % (WP / TW)) * TW;
    const int y0 = (tile / (WP / TW)) * TH;
    const int tid = threadIdx.x;

    // Tile base into the idx-selected kernel slab (pixel p = y*256+x).
    const float* kpt = kernels + (size_t)idx[0] * (KS * KS) * (size_t)PIX
                               + (size_t)y0 * WP + x0;

    const uint32_t wbuf_s = (uint32_t)__cvta_generic_to_shared(wbuf);

    // ---- weight stage prefetch: stage kh -> wbuf[buf] via cp.async ----
    // granule g: tap = g>>5, row = (g&31)>>3, x16 = g&7 (16B = 4 floats)
    auto prefetch_stage = [&](int kh, int buf) {
        #pragma unroll
        for (int it = 0; it < (WGRAN + THREADS - 1) / THREADS; it++) {
            const int g = tid + it * THREADS;
            if (g < WGRAN) {
                const int tap = g >> 5;
                const int row = (g & 31) >> 3;
                const int x16 = g & 7;
                const float* src = kpt + (size_t)(kh * KS + tap) * PIX + row * WP + x16 * 4;
                const uint32_t dst = wbuf_s + (uint32_t)(buf * WSTAGE_FLT + tap * (TH * TW) + row * TW + x16 * 4) * 4u;
                cp_async16(dst, src);
            }
        }
        cp_commit();
    };

    // Kick the first two weight stages before the img load (get DRAM busy).
    prefetch_stage(0, 0);
    prefetch_stage(1, 1);

    // ---- cooperative img tile load: 12 planes x 20 rows x 12 float4/row ----
    {
        const int row4 = SCOLS / 4;                 // 12
        const int total4 = NBC * SROWS * row4;      // 2880
        #pragma unroll 6
        for (int i = tid; i < total4; i += THREADS) {
            const int c4 = i % row4;
            const int r  = (i / row4) % SROWS;
            const int bc = i / (row4 * SROWS);
            const float4 v = *(const float4*)(img + ((size_t)bc * IH + (y0 + r)) * IW + x0 + c4 * 4);
            *(float4*)(simg + (bc * SROWS + r) * SCOLS + c4 * 4) = v;
        }
    }
    __syncthreads();

    // ---- group g = warp g handles planes [4g, 4g+4); each thread a 4-px quad ----
    const int grp    = tid / PXT;         // 0..2
    const int wg_tid = tid % PXT;         // 0..31
    const int qx = wg_tid & 7;            // x quad 0..7
    const int ty = wg_tid >> 3;           // row 0..3
    const int lx = qx * 4;
    const int p  = (y0 + ty) * WP + x0 + lx;
    const int bc0 = grp * PL;

    float4 acc[PL];
    #pragma unroll
    for (int q = 0; q < PL; q++) acc[q] = make_float4(0.f, 0.f, 0.f, 0.f);

    for (int kh = 0; kh < KS; kh++) {
        // Stage kh is one commit-group older than kh+1: wait_group(1) drains it.
        if (kh == KS - 1) cp_wait<0>(); else cp_wait<1>();
        __syncthreads();   // make all threads' cp.async contributions visible

        const float* wcur = wbuf + (kh & 1) * WSTAGE_FLT;

        // 17 per-quad weight float4s from SMEM (conflict-free: warp spans 512B/kw).
        float4 w[KS];
        #pragma unroll
        for (int kw = 0; kw < KS; kw++)
            w[kw] = *(const float4*)(wcur + kw * (TH * TW) + ty * TW + lx);

        #pragma unroll
        for (int q = 0; q < PL; q++) {
            // 20-wide img span for this (plane, kh) row: 5 aligned LDS.128,
            // reused by all 17 taps.
            const float* row = simg + ((bc0 + q) * SROWS + (ty + kh)) * SCOLS + lx;
            float iv[KS + 3];
            #pragma unroll
            for (int j = 0; j < KS + 3; j += 4) {
                const float4 t = *(const float4*)(row + j);
                iv[j] = t.x; iv[j + 1] = t.y; iv[j + 2] = t.z; iv[j + 3] = t.w;
            }
            #pragma unroll
            for (int kw = 0; kw < KS; kw++) {
                acc[q].x = fmaf(w[kw].x, iv[kw],     acc[q].x);
                acc[q].y = fmaf(w[kw].y, iv[kw + 1], acc[q].y);
                acc[q].z = fmaf(w[kw].z, iv[kw + 2], acc[q].z);
                acc[q].w = fmaf(w[kw].w, iv[kw + 3], acc[q].w);
            }
        }

        __syncthreads();   // all warps done reading buf (kh&1) before reuse
        if (kh + 2 < KS) prefetch_stage(kh + 2, kh & 1);
    }

    #pragma unroll
    for (int q = 0; q < PL; q++)
        *(float4*)(out + (size_t)(bc0 + q) * PIX + p) = acc[q];
}

extern "C" void kernel_launch(void* const* d_in, const int* in_sizes, int n_in,
                              void* d_out, int out_size)
{
    const float* img     = (const float*)d_in[0];
    const float* kernels = (const float*)d_in[1];
    const int*   idx     = (const int*)d_in[2];
    float*       out     = (float*)d_out;

    static bool attr_set = false;
    if (!attr_set) {
        cudaFuncSetAttribute(blur_tiled_kernel,
                             cudaFuncAttributeMaxDynamicSharedMemorySize,
                             SMEM_BYTES);
        attr_set = true;
    }

    const int grid = (WP / TW) * (HP / TH);  // 8 * 64 = 512 tiles
    blur_tiled_kernel<<<grid, THREADS, SMEM_BYTES>>>(img, kernels, idx, out);
}